// round 14
// baseline (speedup 1.0000x reference)
#include <cuda_runtime.h>

// GRITAttention — counting sort, unfused accum + persistent tf32 TENSOR GEMM.
// R13: k_out v6 — split-precision tf32 mma.sync (ah@wh + ah@wl + al@wh),
// W hi/lo fully smem-resident per persistent block, conflict-free interleaved
// fragment layouts, K-chunked A with register accumulators.

#define DM 128
#define DE 64
#define MAX_NODES 200000
#define MAX_E     600000

typedef unsigned long long ull;

// ---------------- device scratch (no allocation allowed) ----------------
__device__ __align__(16) float g_wqa[DM];
__device__ __align__(16) float g_wka[DM];
__device__ __align__(16) float g_wewa[DE];
__device__ float g_cbias;
__device__ int   g_is64;

__device__ __align__(16) float g_qa[MAX_NODES];
__device__ __align__(16) float g_ka[MAX_NODES];
__device__ __align__(16) float g_attsum[MAX_NODES];
__device__ __align__(16) float g_alphasum[MAX_NODES];
__device__ __align__(16) float g_attexp[MAX_E];
__device__ __align__(16) float g_accx[(size_t)MAX_NODES * DM];
__device__ __align__(16) float g_acc64[(size_t)MAX_NODES * DE];

// sort structures
__device__ __align__(16) int  g_hist[MAX_NODES];
__device__ __align__(16) int  g_segstart[MAX_NODES];
__device__ __align__(16) int  g_cursor[MAX_NODES];
__device__ __align__(16) int  g_blocksum[1024];
__device__ __align__(16) int2 g_epair[MAX_E];          // {gsrc, gdst}
__device__ __align__(16) int4 g_sp[MAX_E];             // {gdst, e, alpha(bits), pad}

// ---------------- helpers ----------------
__device__ __forceinline__ int ld_idx(const void* p, long long i, int is64) {
    if (is64) return (int)((const long long*)p)[i];
    return ((const int*)p)[i];
}
__device__ __forceinline__ unsigned to_tf32(float x) {
    unsigned r;
    asm("cvt.rna.tf32.f32 %0, %1;" : "=r"(r) : "f"(x));
    return r;
}
__device__ __forceinline__ void mma_tf32(float* c, unsigned a0, unsigned a1,
                                         unsigned a2, unsigned a3,
                                         unsigned b0, unsigned b1) {
    asm("mma.sync.aligned.m16n8k8.row.col.f32.tf32.tf32.f32 "
        "{%0,%1,%2,%3}, {%4,%5,%6,%7}, {%8,%9}, {%0,%1,%2,%3};"
        : "+f"(c[0]), "+f"(c[1]), "+f"(c[2]), "+f"(c[3])
        : "r"(a0), "r"(a1), "r"(a2), "r"(a3), "r"(b0), "r"(b1));
}

// ---------------- kernels ----------------

// merged: zero (blocks 0..gridDim-2) + prep + dtype-detect (last block)
__global__ void k_init(const float* __restrict__ Wq, const float* __restrict__ bq,
                       const float* __restrict__ Wk, const float* __restrict__ bk,
                       const float* __restrict__ Wew, const float* __restrict__ bew,
                       const float* __restrict__ Wa, const int* __restrict__ ei,
                       int nodes) {
    if (blockIdx.x == gridDim.x - 1) {
        int t = threadIdx.x;
        if (t < DM) {
            float s1 = 0.f, s2 = 0.f;
            for (int j = 0; j < DM; j++) {
                float w = Wa[j];
                s1 += Wq[t * DM + j] * w;
                s2 += Wk[t * DM + j] * w;
            }
            g_wqa[t] = s1;
            g_wka[t] = s2;
        } else if (t < DM + DE) {
            int r = t - DM;
            float s = 0.f;
            for (int c = 0; c < DM; c++) s += Wew[r * DM + c] * Wa[c];
            g_wewa[r] = s;
        } else if (t == DM + DE) {
            float s = 0.f;
            for (int j = 0; j < DM; j++) s += (bq[j] + bk[j] + bew[j]) * Wa[j];
            g_cbias = s;
        } else if (t == DM + DE + 1) {
            g_is64 = ((ei[1] | ei[3] | ei[5] | ei[7]) == 0) ? 1 : 0;
        }
    } else {
        int i = blockIdx.x * blockDim.x + threadIdx.x;
        int stride = (gridDim.x - 1) * blockDim.x;
        for (int j = i; j < nodes; j += stride) { g_attsum[j] = 0.f; g_hist[j] = 0; }
    }
}

// per-node scalars qa = x·wqa, ka = x·wka  (one warp per FOUR nodes -> MLP 4)
__global__ void k_qaka(const float* __restrict__ x, int nodes) {
    int w = (blockIdx.x * blockDim.x + threadIdx.x) >> 5;
    int lane = threadIdx.x & 31;
    int g0 = w * 4;
    if (g0 >= nodes) return;
    const float4* x4 = (const float4*)x;
    float4 wq = ((const float4*)g_wqa)[lane];
    float4 wk = ((const float4*)g_wka)[lane];
    float pq[4], pk[4];
    float4 a[4];
    #pragma unroll
    for (int j = 0; j < 4; j++) {
        int gi = (g0 + j < nodes) ? g0 + j : g0;
        a[j] = x4[(size_t)gi * 32 + lane];
    }
    #pragma unroll
    for (int j = 0; j < 4; j++) {
        pq[j] = a[j].x * wq.x + a[j].y * wq.y + a[j].z * wq.z + a[j].w * wq.w;
        pk[j] = a[j].x * wk.x + a[j].y * wk.y + a[j].z * wk.z + a[j].w * wk.w;
    }
    #pragma unroll
    for (int off = 16; off; off >>= 1) {
        #pragma unroll
        for (int j = 0; j < 4; j++) {
            pq[j] += __shfl_down_sync(0xffffffffu, pq[j], off);
            pk[j] += __shfl_down_sync(0xffffffffu, pk[j], off);
        }
    }
    if (lane == 0) {
        #pragma unroll
        for (int j = 0; j < 4; j++) {
            if (g0 + j < nodes) { g_qa[g0 + j] = pq[j]; g_ka[g0 + j] = pk[j]; }
        }
    }
}

// pass 1: per edge logit -> exp, denominator per gdst, histogram per gsrc,
// cache (gsrc,gdst). 8 lanes/edge.
__global__ void k_edge1(const void* __restrict__ ei, const float* __restrict__ emb,
                        const void* __restrict__ bi, int E, int Nn) {
    int gid = blockIdx.x * blockDim.x + threadIdx.x;
    int e = gid >> 3;
    int l = gid & 7;
    bool valid = e < E;
    int ec = valid ? e : 0;
    const float4* e4 = (const float4*)emb;
    float4 a = e4[(size_t)ec * 16 + l * 2];
    float4 b = e4[(size_t)ec * 16 + l * 2 + 1];
    float4 w1 = ((const float4*)g_wewa)[l * 2];
    float4 w2 = ((const float4*)g_wewa)[l * 2 + 1];
    float p = a.x * w1.x + a.y * w1.y + a.z * w1.z + a.w * w1.w
            + b.x * w2.x + b.y * w2.y + b.z * w2.z + b.w * w2.w;
    p += __shfl_down_sync(0xffffffffu, p, 4, 8);
    p += __shfl_down_sync(0xffffffffu, p, 2, 8);
    p += __shfl_down_sync(0xffffffffu, p, 1, 8);
    if (valid && l == 0) {
        int is64 = g_is64;
        int s  = ld_idx(ei, e, is64);
        int d  = ld_idx(ei, (long long)E + e, is64);
        int bb = ld_idx(bi, e, is64);
        int gsrc = bb * Nn + s;
        int gdst = bb * Nn + d;
        g_epair[e] = make_int2(gsrc, gdst);
        float logit = (g_qa[gsrc] + g_ka[gdst] + p + g_cbias) * 0.25f; // 1/sqrt(16)
        float ex = expf(logit);
        g_attexp[e] = ex;
        atomicAdd(&g_attsum[gdst], ex);
        atomicAdd(&g_hist[gsrc], 1);
    }
}

// ---- 3-step exclusive scan of g_hist ----
__global__ void k_scan1(int nodes) {
    __shared__ int s[256];
    int i = blockIdx.x * 256 + threadIdx.x;
    int v = (i < nodes) ? g_hist[i] : 0;
    s[threadIdx.x] = v;
    __syncthreads();
    #pragma unroll
    for (int off = 128; off; off >>= 1) {
        if (threadIdx.x < off) s[threadIdx.x] += s[threadIdx.x + off];
        __syncthreads();
    }
    if (threadIdx.x == 0) g_blocksum[blockIdx.x] = s[0];
}

__global__ void k_scan2(int nb) {
    __shared__ int s[1024];
    int t = threadIdx.x;
    int v = (t < nb) ? g_blocksum[t] : 0;
    s[t] = v;
    __syncthreads();
    #pragma unroll
    for (int off = 1; off < 1024; off <<= 1) {
        int add = (t >= off) ? s[t - off] : 0;
        __syncthreads();
        s[t] += add;
        __syncthreads();
    }
    if (t < nb) g_blocksum[t] = s[t] - v;   // exclusive
}

__global__ void k_scan3(int nodes) {
    __shared__ int s[256];
    int i = blockIdx.x * 256 + threadIdx.x;
    int v = (i < nodes) ? g_hist[i] : 0;
    s[threadIdx.x] = v;
    __syncthreads();
    #pragma unroll
    for (int off = 1; off < 256; off <<= 1) {
        int add = (threadIdx.x >= off) ? s[threadIdx.x - off] : 0;
        __syncthreads();
        s[threadIdx.x] += add;
        __syncthreads();
    }
    if (i < nodes) {
        int start = g_blocksum[blockIdx.x] + s[threadIdx.x] - v;
        g_segstart[i] = start;
        g_cursor[i]   = start;
    }
}

// scatter: per edge, compute alpha, place packed payload into gsrc-sorted slot
__global__ void k_scatter(int E) {
    int e = blockIdx.x * blockDim.x + threadIdx.x;
    if (e >= E) return;
    int2 pr = g_epair[e];
    float alpha = g_attexp[e] / (g_attsum[pr.y] + 1e-9f);
    int pos = atomicAdd(&g_cursor[pr.x], 1);
    g_sp[pos] = make_int4(pr.y, e, __float_as_int(alpha), 0);
}

// segmented accumulation: one warp per node, registers only, 4-wide MLP
__global__ void k_accum(const float* __restrict__ x, const float* __restrict__ emb,
                        int nodes) {
    int g = (blockIdx.x * blockDim.x + threadIdx.x) >> 5;
    int lane = threadIdx.x & 31;
    if (g >= nodes) return;
    int i   = g_segstart[g];
    int end = g_cursor[g];
    const float4* x4 = (const float4*)x;
    const float2* e2 = (const float2*)emb;
    float4 ax = make_float4(0.f, 0.f, 0.f, 0.f);
    float2 ae = make_float2(0.f, 0.f);
    float asum = 0.f;
    for (; i + 3 < end; i += 4) {
        int4 p0 = __ldg(&g_sp[i]);
        int4 p1 = __ldg(&g_sp[i + 1]);
        int4 p2 = __ldg(&g_sp[i + 2]);
        int4 p3 = __ldg(&g_sp[i + 3]);
        float a0 = __int_as_float(p0.z), a1 = __int_as_float(p1.z);
        float a2 = __int_as_float(p2.z), a3 = __int_as_float(p3.z);
        float4 xv0 = x4[(size_t)p0.x * 32 + lane];
        float4 xv1 = x4[(size_t)p1.x * 32 + lane];
        float4 xv2 = x4[(size_t)p2.x * 32 + lane];
        float4 xv3 = x4[(size_t)p3.x * 32 + lane];
        float2 ev0 = e2[(size_t)p0.y * 32 + lane];
        float2 ev1 = e2[(size_t)p1.y * 32 + lane];
        float2 ev2 = e2[(size_t)p2.y * 32 + lane];
        float2 ev3 = e2[(size_t)p3.y * 32 + lane];
        ax.x += a0 * xv0.x + a1 * xv1.x + a2 * xv2.x + a3 * xv3.x;
        ax.y += a0 * xv0.y + a1 * xv1.y + a2 * xv2.y + a3 * xv3.y;
        ax.z += a0 * xv0.z + a1 * xv1.z + a2 * xv2.z + a3 * xv3.z;
        ax.w += a0 * xv0.w + a1 * xv1.w + a2 * xv2.w + a3 * xv3.w;
        ae.x += a0 * ev0.x + a1 * ev1.x + a2 * ev2.x + a3 * ev3.x;
        ae.y += a0 * ev0.y + a1 * ev1.y + a2 * ev2.y + a3 * ev3.y;
        asum += (a0 + a1) + (a2 + a3);
    }
    for (; i + 1 < end; i += 2) {
        int4 p0 = __ldg(&g_sp[i]);
        int4 p1 = __ldg(&g_sp[i + 1]);
        float a0 = __int_as_float(p0.z), a1 = __int_as_float(p1.z);
        float4 xv0 = x4[(size_t)p0.x * 32 + lane];
        float4 xv1 = x4[(size_t)p1.x * 32 + lane];
        float2 ev0 = e2[(size_t)p0.y * 32 + lane];
        float2 ev1 = e2[(size_t)p1.y * 32 + lane];
        ax.x += a0 * xv0.x + a1 * xv1.x;
        ax.y += a0 * xv0.y + a1 * xv1.y;
        ax.z += a0 * xv0.z + a1 * xv1.z;
        ax.w += a0 * xv0.w + a1 * xv1.w;
        ae.x += a0 * ev0.x + a1 * ev1.x;
        ae.y += a0 * ev0.y + a1 * ev1.y;
        asum += a0 + a1;
    }
    if (i < end) {
        int4 p = __ldg(&g_sp[i]);
        float a = __int_as_float(p.z);
        float4 xv = x4[(size_t)p.x * 32 + lane];
        float2 ev = e2[(size_t)p.y * 32 + lane];
        ax.x += a * xv.x; ax.y += a * xv.y; ax.z += a * xv.z; ax.w += a * xv.w;
        ae.x += a * ev.x; ae.y += a * ev.y;
        asum += a;
    }
    ((float4*)g_accx)[(size_t)g * 32 + lane] = ax;
    ((float2*)g_acc64)[(size_t)g * 32 + lane] = ae;
    if (lane == 0) g_alphasum[g] = asum;
}

// PERSISTENT tf32 TENSOR GEMM: out = [accx|acc64] @ [[Wv];[Wev]] + alphasum*(bv+bev)
// 148 blocks x 256 threads. W hi/lo resident in smem (interleaved [k/4][n][k%4]
// -> B-fragment loads are base+lane, conflict-free). A chunks 64 rows x 64 k,
// hi/lo, interleaved [k/4][m][k%4] -> A-fragment loads base+lane. 3 mma passes.
#define KOUT_BLOCKS 148
#define KC 64
// smem float offsets
#define OFF_WH 0
#define OFF_WL (192 * 128)
#define OFF_AH (2 * 192 * 128)
#define OFF_AL (2 * 192 * 128 + 64 * KC)
#define OFF_B  (2 * 192 * 128 + 2 * 64 * KC)
#define SMEM_FLOATS (2 * 192 * 128 + 2 * 64 * KC + 128)

__global__ void __launch_bounds__(256)
k_out(const float* __restrict__ Wv, const float* __restrict__ bv,
      const float* __restrict__ Wev, const float* __restrict__ bev,
      float* __restrict__ out, int nodes) {
    extern __shared__ float smem[];
    float* sWh = smem + OFF_WH;
    float* sWl = smem + OFF_WL;
    float* sAh = smem + OFF_AH;
    float* sAl = smem + OFF_AL;
    float* sB  = smem + OFF_B;

    int tid  = threadIdx.x;
    int lane = tid & 31;
    int wid  = tid >> 5;
    int mg   = wid & 3;      // warp row-group: rows mg*16 .. mg*16+15
    int nh   = wid >> 2;     // warp col-half: cols nh*64 .. nh*64+63
    int grp  = lane >> 2;    // groupID 0..7
    int tig  = lane & 3;     // thread-in-group

    // ---- bias sum ----
    if (tid < 128) sB[tid] = bv[tid] + bev[tid];

    // ---- load full W (hi/lo tf32 split), interleaved layout, once ----
    // addr(k, n) = (k>>2)*512 + n*4 + (k&3)
    #pragma unroll
    for (int t = 0; t < 24; t++) {
        int i4 = tid + t * 256;          // 0..6143
        int k  = i4 >> 5;                // 0..191
        int c4 = (i4 & 31) << 2;
        float4 v = (k < 128) ? *(const float4*)&Wv[k * DM + c4]
                             : *(const float4*)&Wev[(k - 128) * DM + c4];
        int base = (k >> 2) * 512 + (k & 3);
        #pragma unroll
        for (int j = 0; j < 4; j++) {
            float w = (&v.x)[j];
            unsigned hb = to_tf32(w);
            float hf = __uint_as_float(hb);
            unsigned lb = to_tf32(w - hf);
            sWh[base + (c4 + j) * 4] = hf;
            sWl[base + (c4 + j) * 4] = __uint_as_float(lb);
        }
    }

    int ntiles = (nodes + 63) >> 6;
    for (int tile = blockIdx.x; tile < ntiles; tile += KOUT_BLOCKS) {
        int g0 = tile << 6;

        float c[8][4];
        #pragma unroll
        for (int nt = 0; nt < 8; nt++)
            #pragma unroll
            for (int j = 0; j < 4; j++) c[nt][j] = 0.f;

        #pragma unroll 1
        for (int kc = 0; kc < 192; kc += KC) {
            __syncthreads();   // prior compute done (or W/B fill on first pass)
            // ---- fill A chunk (64 rows x KC k), hi/lo, interleaved ----
            // addr(kl, m) = (kl>>2)*256 + m*4 + (kl&3)
            {
                int m   = tid & 63;
                int sub = tid >> 6;                  // 0..3
                int gm  = g0 + m; if (gm >= nodes) gm = nodes - 1;
                const float* arow = &g_accx[(size_t)gm * DM];
                const float* erow = &g_acc64[(size_t)gm * DE];
                #pragma unroll
                for (int t = 0; t < 4; t++) {
                    int kl = (sub + t * 4) << 2;     // 0..60 step 4
                    int kg = kc + kl;
                    float4 v = (kg < 128) ? *(const float4*)&arow[kg]
                                          : *(const float4*)&erow[kg - 128];
                    float4 hi, lo;
                    #pragma unroll
                    for (int j = 0; j < 4; j++) {
                        float a = (&v.x)[j];
                        unsigned hb = to_tf32(a);
                        float hf = __uint_as_float(hb);
                        (&hi.x)[j] = hf;
                        (&lo.x)[j] = __uint_as_float(to_tf32(a - hf));
                    }
                    int dst = (kl >> 2) * 256 + m * 4;
                    *(float4*)&sAh[dst] = hi;
                    *(float4*)&sAl[dst] = lo;
                }
            }
            __syncthreads();

            // ---- compute: 8 k-steps of 8 ----
            #pragma unroll
            for (int ks = 0; ks < 8; ks++) {
                int kb = kc + ks * 8;                       // global k (for W)
                int ab = (ks * 2) * 256 + mg * 64 + lane;   // A frag base
                unsigned ah0 = __float_as_uint(sAh[ab]);
                unsigned ah1 = __float_as_uint(sAh[ab + 32]);
                unsigned ah2 = __float_as_uint(sAh[ab + 256]);
                unsigned ah3 = __float_as_uint(sAh[ab + 288]);
                unsigned al0 = __float_as_uint(sAl[ab]);
                unsigned al1 = __float_as_uint(sAl[ab + 32]);
                unsigned al2 = __float_as_uint(sAl[ab + 256]);
                unsigned al3 = __float_as_uint(sAl[ab + 288]);
                int wbase = (kb >> 2) * 512 + nh * 256 + lane;
                #pragma unroll
                for (int nt = 0; nt < 8; nt++) {
                    int bb = wbase + nt * 32;
                    unsigned bh0 = __float_as_uint(sWh[bb]);
                    unsigned bh1 = __float_as_uint(sWh[bb + 512]);
                    unsigned bl0 = __float_as_uint(sWl[bb]);
                    unsigned bl1 = __float_as_uint(sWl[bb + 512]);
                    mma_tf32(c[nt], ah0, ah1, ah2, ah3, bh0, bh1);
                    mma_tf32(c[nt], ah0, ah1, ah2, ah3, bl0, bl1);
                    mma_tf32(c[nt], al0, al1, al2, al3, bh0, bh1);
                }
            }
        }

        // ---- epilogue: C frag rows mg*16+grp(+8), cols n0+2*tig(+1) ----
        int r0 = g0 + mg * 16 + grp;
        int r1 = r0 + 8;
        float as0 = (r0 < nodes) ? g_alphasum[r0] : 0.f;
        float as1 = (r1 < nodes) ? g_alphasum[r1] : 0.f;
        #pragma unroll
        for (int nt = 0; nt < 8; nt++) {
            int col = nh * 64 + nt * 8 + 2 * tig;
            float b0 = sB[col], b1 = sB[col + 1];
            if (r0 < nodes) {
                float2 o = make_float2(c[nt][0] + as0 * b0, c[nt][1] + as0 * b1);
                *(float2*)&out[(size_t)r0 * DM + col] = o;
            }
            if (r1 < nodes) {
                float2 o = make_float2(c[nt][2] + as1 * b0, c[nt][3] + as1 * b1);
                *(float2*)&out[(size_t)r1 * DM + col] = o;
            }
        }
    }
}

// ---------------- launcher ----------------
extern "C" void kernel_launch(void* const* d_in, const int* in_sizes, int n_in,
                              void* d_out, int out_size) {
    const float* x   = (const float*)d_in[0];
    const void*  ei  = d_in[1];
    const float* emb = (const float*)d_in[2];
    const void*  bi  = d_in[3];
    int base = 4;
    if (n_in >= 16 && in_sizes[4] <= 2) base = 5;
    const float* Wq  = (const float*)d_in[base + 0];
    const float* bq  = (const float*)d_in[base + 1];
    const float* Wk  = (const float*)d_in[base + 2];
    const float* bk  = (const float*)d_in[base + 3];
    const float* Wv  = (const float*)d_in[base + 4];
    const float* bv  = (const float*)d_in[base + 5];
    const float* Wew = (const float*)d_in[base + 6];
    const float* bew = (const float*)d_in[base + 7];
    const float* Wev = (const float*)d_in[base + 8];
    const float* bev = (const float*)d_in[base + 9];
    const float* Wa  = (const float*)d_in[base + 10];

    int nodes = in_sizes[0] / DM;   // B*N
    int E     = in_sizes[3];
    int Nn    = nodes / 4;          // N (B = 4)
    int nb    = (nodes + 255) / 256;

    // smem: 2*24576 (W hi/lo) + 2*4096 (A hi/lo) + 128 (bias) floats = 229888 B
    int smem_bytes = SMEM_FLOATS * (int)sizeof(float);
    cudaFuncSetAttribute(k_out, cudaFuncAttributeMaxDynamicSharedMemorySize, smem_bytes);

    k_init<<<257, 256>>>(Wq, bq, Wk, bk, Wew, bew, Wa, (const int*)ei, nodes);
    k_qaka<<<(nodes / 4 + 7) / 8, 256>>>(x, nodes);
    k_edge1<<<(E + 31) / 32, 256>>>(ei, emb, bi, E, Nn);
    k_scan1<<<nb, 256>>>(nodes);
    k_scan2<<<1, 1024>>>(nb);
    k_scan3<<<nb, 256>>>(nodes);
    k_scatter<<<(E + 255) / 256, 256>>>(E);
    k_accum<<<(nodes + 7) / 8, 256>>>(x, emb, nodes);
    k_out<<<KOUT_BLOCKS, 256, smem_bytes>>>(Wv, bv, Wev, bev, (float*)d_out, nodes);
}